// round 2
// baseline (speedup 1.0000x reference)
#include <cuda_runtime.h>
#include <cuda_bf16.h>
#include <math.h>

#define BB 8
#define SS 4096
#define DD 1024
#define FF 512
#define M_TOTAL (BB*SS)   // 32768
#define MAXP 8

// ---- scratch (static __device__ = allowed; allocated at module load) ----
__device__ unsigned int g_Wpk[(DD/2)*FF];   // W1 packed as bf16 k-pairs: [kk][n]
__device__ float g_partial[M_TOTAL*8];      // per-row logit partials (8 slots)
__device__ float g_scores[M_TOTAL];
__device__ float g_norm2[M_TOTAL];
__device__ float g_dot[M_TOTAL];            // dot(x_s, x_{s+1}) within batch
__device__ float g_pooled[BB*MAXP*DD];
__device__ int g_first, g_last;

// ================= prep: pack W1 -> bf16 pairs, reset bounds ==============
__global__ void k_prep(const float* __restrict__ W1) {
    int idx = blockIdx.x*blockDim.x + threadIdx.x;
    if (idx == 0) { g_first = 0x7fffffff; g_last = -1; }
    if (idx < (DD/2)*FF) {
        int kk = idx / FF, n = idx % FF;
        unsigned short lo = __bfloat16_as_ushort(__float2bfloat16(W1[(size_t)(2*kk)*FF + n]));
        unsigned short hi = __bfloat16_as_ushort(__float2bfloat16(W1[(size_t)(2*kk+1)*FF + n]));
        g_Wpk[idx] = ((unsigned int)hi << 16) | (unsigned int)lo;
    }
}

// ================= big GEMM: X(32768x1024) @ W1(1024x512), fused epilogue ==
#define BM 128
#define BN 128
#define BK 32
#define ASTRIDE 40    // bf16 elems, pad for bank conflicts
#define BSTRIDE 136   // uint32 words, pad

__device__ __forceinline__ void mma16816(float* d, const unsigned* a, unsigned b0, unsigned b1){
    asm volatile(
      "mma.sync.aligned.m16n8k16.row.col.f32.bf16.bf16.f32 "
      "{%0,%1,%2,%3}, {%4,%5,%6,%7}, {%8,%9}, {%0,%1,%2,%3};\n"
      : "+f"(d[0]), "+f"(d[1]), "+f"(d[2]), "+f"(d[3])
      : "r"(a[0]), "r"(a[1]), "r"(a[2]), "r"(a[3]), "r"(b0), "r"(b1));
}

__global__ __launch_bounds__(256) void k_gemm(const float* __restrict__ Ag,
                                              const float* __restrict__ b1,
                                              const float* __restrict__ w2) {
    __shared__ __nv_bfloat16 As[BM*ASTRIDE];
    __shared__ unsigned int  Bs[16*BSTRIDE];
    const int nc  = blockIdx.x;          // 0..3 (N chunk of 128)
    const int m0  = blockIdx.y * BM;     // row tile
    const int n0  = nc * BN;
    const int tid = threadIdx.x;
    const int warp = tid >> 5, lane = tid & 31;
    const int warpM = warp >> 1, warpN = warp & 1;   // 4 x 2 warp grid
    const int lr = lane >> 2, qc = lane & 3;

    float acc[2][8][4];
    #pragma unroll
    for (int mt=0; mt<2; mt++)
      #pragma unroll
      for (int nt=0; nt<8; nt++)
        #pragma unroll
        for (int e=0; e<4; e++) acc[mt][nt][e] = 0.f;

    for (int kt = 0; kt < DD/BK; kt++) {
        __syncthreads();
        // stage A tile (convert f32 -> bf16)
        #pragma unroll
        for (int i=0;i<8;i++){
            int idx = tid + i*256;
            int r = idx >> 4, kc = (idx & 15) * 2;
            float2 v = *(const float2*)(Ag + (size_t)(m0+r)*DD + kt*BK + kc);
            *(__nv_bfloat162*)(As + r*ASTRIDE + kc) = __float22bfloat162_rn(v);
        }
        // stage B tile (already packed bf16 pairs)
        #pragma unroll
        for (int i=0;i<8;i++){
            int idx = tid + i*256;
            int kk = idx >> 7, n = idx & 127;
            Bs[kk*BSTRIDE + n] = g_Wpk[(size_t)(kt*16+kk)*FF + n0 + n];
        }
        __syncthreads();
        #pragma unroll
        for (int ks=0; ks<2; ks++){
            unsigned int a[2][4];
            #pragma unroll
            for (int mt=0; mt<2; mt++){
                const __nv_bfloat16* base = As + (warpM*32 + mt*16 + lr)*ASTRIDE + ks*16 + qc*2;
                a[mt][0] = *(const unsigned int*)(base);
                a[mt][1] = *(const unsigned int*)(base + 8*ASTRIDE);
                a[mt][2] = *(const unsigned int*)(base + 8);
                a[mt][3] = *(const unsigned int*)(base + 8*ASTRIDE + 8);
            }
            #pragma unroll
            for (int nt=0; nt<8; nt++){
                int ncol = warpN*64 + nt*8 + lr;
                unsigned int bb0 = Bs[(ks*8   + qc)*BSTRIDE + ncol];
                unsigned int bb1 = Bs[(ks*8+4 + qc)*BSTRIDE + ncol];
                mma16816(acc[0][nt], a[0], bb0, bb1);
                mma16816(acc[1][nt], a[1], bb0, bb1);
            }
        }
    }

    // epilogue: per-row sum over this CTA's 128 cols of relu(h+b1)*w2
    float b1r[16], w2r[16];
    #pragma unroll
    for (int nt=0; nt<8; nt++){
        #pragma unroll
        for (int e=0; e<2; e++){
            int n = n0 + warpN*64 + nt*8 + qc*2 + e;
            b1r[nt*2+e] = b1[n];
            w2r[nt*2+e] = w2[n];
        }
    }
    #pragma unroll
    for (int mt=0; mt<2; mt++){
        float sA = 0.f, sB = 0.f;
        #pragma unroll
        for (int nt=0; nt<8; nt++){
            #pragma unroll
            for (int e=0; e<2; e++){
                float bv = b1r[nt*2+e], wv = w2r[nt*2+e];
                sA += fmaxf(acc[mt][nt][e]   + bv, 0.f) * wv;
                sB += fmaxf(acc[mt][nt][2+e] + bv, 0.f) * wv;
            }
        }
        sA += __shfl_xor_sync(0xffffffffu, sA, 1);
        sA += __shfl_xor_sync(0xffffffffu, sA, 2);
        sB += __shfl_xor_sync(0xffffffffu, sB, 1);
        sB += __shfl_xor_sync(0xffffffffu, sB, 2);
        if (qc == 0){
            int rA = m0 + warpM*32 + mt*16 + lr;
            g_partial[(size_t)rA*8     + nc*2 + warpN] = sA;
            g_partial[(size_t)(rA+8)*8 + nc*2 + warpN] = sB;
        }
    }
}

// ================= scores: sigmoid(b2 + sum partials) ======================
__global__ void k_score(const float* __restrict__ b2){
    int i = blockIdx.x*256 + threadIdx.x;
    if (i < M_TOTAL){
        float l = b2[0];
        #pragma unroll
        for (int j=0;j<8;j++) l += g_partial[(size_t)i*8 + j];
        g_scores[i] = 1.f / (1.f + expf(-l));
    }
}

// ================= norms + adjacent dots ===================================
__global__ void k_cos(const float* __restrict__ X){
    int s = blockIdx.x;
    int t = s & (SS-1);
    bool pair = (t < SS-1);
    const float4* xa = (const float4*)(X + (size_t)s*DD);
    int tid = threadIdx.x;                  // 256 threads, D/4 = 256 float4
    float4 a = xa[tid];
    float n2 = a.x*a.x + a.y*a.y + a.z*a.z + a.w*a.w;
    float dt = 0.f;
    if (pair){
        float4 b = xa[DD/4 + tid];
        dt = a.x*b.x + a.y*b.y + a.z*b.z + a.w*b.w;
    }
    // block reduce (8 warps)
    #pragma unroll
    for (int o=16;o>0;o>>=1){
        n2 += __shfl_xor_sync(0xffffffffu, n2, o);
        dt += __shfl_xor_sync(0xffffffffu, dt, o);
    }
    __shared__ float sn[8], sd[8];
    int w = tid >> 5;
    if ((tid & 31) == 0){ sn[w] = n2; sd[w] = dt; }
    __syncthreads();
    if (tid == 0){
        float N = 0.f, Dt = 0.f;
        #pragma unroll
        for (int j=0;j<8;j++){ N += sn[j]; Dt += sd[j]; }
        g_norm2[s] = N;
        g_dot[s]   = Dt;
    }
}

// ================= EOS rules + global bounds ===============================
__global__ void k_rule(){
    int i = blockIdx.x*256 + threadIdx.x;
    if (i >= M_TOTAL) return;
    int t = i & (SS-1);
    if (t < 2) return;
    float sc = g_scores[i];
    bool run = (sc > 0.7f) && (g_scores[i-1] > 0.7f) && (g_scores[i-2] > 0.7f);
    float na = fmaxf(sqrtf(g_norm2[i-1]), 1e-8f);
    float nb = fmaxf(sqrtf(g_norm2[i]),   1e-8f);
    float cosv = g_dot[i-1] / (na * nb);
    bool cr = (cosv < 0.3f) && (sc > 0.5f);
    if (run || cr){
        atomicMin(&g_first, t);
        atomicMax(&g_last,  t);
    }
}

// ================= segment pooling (prefix only matters) ===================
__global__ void k_pool(const float* __restrict__ X, const int* __restrict__ Mk){
    __shared__ float ssum[MAXP*DD];   // 32KB
    __shared__ int   scnt[MAXP];
    int b = blockIdx.x;
    int tid = threadIdx.x;            // 256
    for (int i = tid; i < MAXP*DD; i += 256) ssum[i] = 0.f;
    if (tid < MAXP) scnt[tid] = 0;
    __syncthreads();
    const float* xb = X + (size_t)b*SS*DD;
    const int*   mb = Mk + (size_t)b*SS;
    int c = 0;
    for (int s = 0; s < SS && c < MAXP; s++){
        #pragma unroll
        for (int j=0;j<4;j++){
            int d = tid + j*256;
            ssum[c*DD + d] += xb[(size_t)s*DD + d];
        }
        if (tid == 0) scnt[c]++;
        c += (mb[s] != 0) ? 1 : 0;
    }
    __syncthreads();
    #pragma unroll
    for (int p=0;p<MAXP;p++){
        float inv = 1.f / (float)max(scnt[p], 1);
        #pragma unroll
        for (int j=0;j<4;j++){
            int d = tid + j*256;
            g_pooled[((size_t)b*MAXP + p)*DD + d] = ssum[p*DD + d] * inv;
        }
    }
}

// ================= patches = pooled @ proj_w + proj_b ======================
__global__ void k_patch(const float* __restrict__ Pw, const float* __restrict__ Pb,
                        float* __restrict__ out){
    __shared__ float ps[MAXP*DD];     // 32KB
    int oc = blockIdx.x, b = blockIdx.y;
    int tid = threadIdx.x;            // 128
    for (int i = tid; i < MAXP*DD; i += 128) ps[i] = g_pooled[(size_t)b*MAXP*DD + i];
    __syncthreads();
    int o = oc*128 + tid;
    float acc[MAXP];
    #pragma unroll
    for (int p=0;p<MAXP;p++) acc[p] = 0.f;
    for (int d=0; d<DD; d++){
        float w = Pw[(size_t)d*DD + o];
        #pragma unroll
        for (int p=0;p<MAXP;p++) acc[p] += ps[p*DD + d] * w;
    }
    float bias = Pb[o];
    #pragma unroll
    for (int p=0;p<MAXP;p++)
        out[((size_t)b*MAXP + p)*DD + o] = acc[p] + bias;
}

// ================= finalize bounds =========================================
__global__ void k_final(float* __restrict__ out, int out_size){
    if (threadIdx.x == 0 && blockIdx.x == 0){
        int f = g_first, l = g_last;
        float s0 = -1.f, s1 = -1.f;
        if (f != 0x7fffffff){
            s0 = (float)max(0, f - 2);
            s1 = (float)min(SS - 1, l + 2);
        }
        if (out_size >= BB*MAXP*DD + 2){
            out[BB*MAXP*DD + 0] = s0;
            out[BB*MAXP*DD + 1] = s1;
        }
    }
}

// ===========================================================================
extern "C" void kernel_launch(void* const* d_in, const int* in_sizes, int n_in,
                              void* d_out, int out_size) {
    const float* latent = (const float*)d_in[0];
    const int*   mask   = (const int*)  d_in[1];
    const float* proj_w = (const float*)d_in[2];
    const float* proj_b = (const float*)d_in[3];
    const float* w1     = (const float*)d_in[4];
    const float* b1     = (const float*)d_in[5];
    const float* w2     = (const float*)d_in[6];
    const float* b2     = (const float*)d_in[7];
    float* out = (float*)d_out;

    k_prep <<< ((DD/2)*FF + 255)/256, 256 >>>(w1);
    k_gemm <<< dim3(4, M_TOTAL/BM), 256 >>>(latent, b1, w2);
    k_score<<< M_TOTAL/256, 256 >>>(b2);
    k_cos  <<< M_TOTAL, 256 >>>(latent);
    k_rule <<< M_TOTAL/256, 256 >>>();
    k_pool <<< BB, 256 >>>(latent, mask);
    k_patch<<< dim3(DD/128, BB), 128 >>>(proj_w, proj_b, out);
    k_final<<< 1, 32 >>>(out, out_size);
}